// round 1
// baseline (speedup 1.0000x reference)
#include <cuda_runtime.h>
#include <math.h>

// MoE Router: T=16384 tokens, D=4096, E=64 experts, top-K=2.
// Outputs concatenated as float32 into d_out:
//   [0,            T*E)              router_logits [T,E]
//   [T*E,          T*E+T*K)          router_weights [T,K]
//   [T*E+T*K,      T*E+2*T*K)        select_expert_indices [T,K] (as float)
//   [T*E+2*T*K,    +E*K*T)           expert_mask [E,K,T] (0.0/1.0)

#define Dk   4096
#define Ek   64
#define TOPK 2
#define TT   64    // tokens per block
#define KC   32    // k-chunk

__global__ void zero_region_kernel(float4* __restrict__ p, int n4) {
    int i = blockIdx.x * blockDim.x + threadIdx.x;
    int stride = gridDim.x * blockDim.x;
    float4 z = make_float4(0.f, 0.f, 0.f, 0.f);
    for (; i < n4; i += stride) p[i] = z;
}

__global__ __launch_bounds__(256)
void moe_router_kernel(const float* __restrict__ x,
                       const float* __restrict__ gw,
                       const float* __restrict__ gb,
                       float* __restrict__ out, int T)
{
    __shared__ float xs[KC][TT + 1];   // +1 pad: store bank = (c+r)%32, conflict-free
    __shared__ float ws[KC][Ek + 1];
    __shared__ float lg[TT][Ek + 1];

    const int t0  = blockIdx.x * TT;
    const int tid = threadIdx.x;
    const int tx  = tid & 15;          // expert group
    const int ty  = tid >> 4;          // token group

    float acc[4][4];
#pragma unroll
    for (int i = 0; i < 4; i++)
#pragma unroll
        for (int j = 0; j < 4; j++) acc[i][j] = 0.f;

    for (int d0 = 0; d0 < Dk; d0 += KC) {
        // x tile: TT rows x KC cols -> xs[c][r]; global coalesced along d
#pragma unroll
        for (int it = 0; it < (TT * KC) / 256; it++) {
            int idx = it * 256 + tid;
            int r = idx >> 5;          // token within tile
            int c = idx & 31;          // k within chunk
            xs[c][r] = x[(size_t)(t0 + r) * Dk + d0 + c];
        }
        // w tile: Ek rows x KC cols -> ws[c][e]
#pragma unroll
        for (int it = 0; it < (Ek * KC) / 256; it++) {
            int idx = it * 256 + tid;
            int e = idx >> 5;
            int c = idx & 31;
            ws[c][e] = gw[(size_t)e * Dk + d0 + c];
        }
        __syncthreads();

#pragma unroll
        for (int kk = 0; kk < KC; kk++) {
            float a[4], b[4];
#pragma unroll
            for (int i = 0; i < 4; i++) a[i] = xs[kk][ty + 16 * i];
#pragma unroll
            for (int j = 0; j < 4; j++) b[j] = ws[kk][tx + 16 * j];
#pragma unroll
            for (int i = 0; i < 4; i++)
#pragma unroll
                for (int j = 0; j < 4; j++)
                    acc[i][j] = fmaf(a[i], b[j], acc[i][j]);
        }
        __syncthreads();
    }

    // epilogue: add bias, store logits (gmem + smem for softmax)
    float bias[4];
#pragma unroll
    for (int j = 0; j < 4; j++) bias[j] = gb[tx + 16 * j];

#pragma unroll
    for (int i = 0; i < 4; i++) {
        int tl = ty + 16 * i;
        int t  = t0 + tl;
#pragma unroll
        for (int j = 0; j < 4; j++) {
            int e = tx + 16 * j;
            float v = acc[i][j] + bias[j];
            lg[tl][e] = v;
            out[(size_t)t * Ek + e] = v;
        }
    }
    __syncthreads();

    // per-token softmax + top-2 + renorm + mask scatter
    if (tid < TT) {
        const int t = t0 + tid;
        float m1 = -INFINITY, m2 = -INFINITY;
        int i1 = 0, i2 = 0;
#pragma unroll 8
        for (int e = 0; e < Ek; e++) {
            float v = lg[tid][e];
            if (v > m1) { m2 = m1; i2 = i1; m1 = v; i1 = e; }
            else if (v > m2) { m2 = v; i2 = e; }
        }
        // renormalized top-2 softmax weights (Z cancels):
        //   w1 = 1/(1+exp(l2-l1)), w2 = exp(l2-l1)*w1
        float ed = expf(m2 - m1);
        float w1 = 1.0f / (1.0f + ed);
        float w2 = ed * w1;

        const size_t offW = (size_t)T * Ek;
        const size_t offI = offW + (size_t)T * TOPK;
        const size_t offM = offI + (size_t)T * TOPK;

        out[offW + (size_t)t * TOPK + 0] = w1;
        out[offW + (size_t)t * TOPK + 1] = w2;
        out[offI + (size_t)t * TOPK + 0] = (float)i1;
        out[offI + (size_t)t * TOPK + 1] = (float)i2;
        // expert_mask[e][k][t]
        out[offM + ((size_t)i1 * TOPK + 0) * (size_t)T + t] = 1.0f;
        out[offM + ((size_t)i2 * TOPK + 1) * (size_t)T + t] = 1.0f;
    }
}

extern "C" void kernel_launch(void* const* d_in, const int* in_sizes, int n_in,
                              void* d_out, int out_size)
{
    const float* x  = (const float*)d_in[0];
    const float* gw = (const float*)d_in[1];
    const float* gb = (const float*)d_in[2];
    float* out = (float*)d_out;

    const int T = in_sizes[0] / Dk;

    // zero the expert_mask region (rest of d_out is fully overwritten)
    const size_t offM = (size_t)T * Ek + 2 * (size_t)T * TOPK;
    const int mask_n4 = (Ek * TOPK * T) / 4;
    zero_region_kernel<<<592, 256>>>((float4*)(out + offM), mask_n4);

    moe_router_kernel<<<T / TT, 256>>>(x, gw, gb, out, T);
}

// round 8
// speedup vs baseline: 3.0822x; 3.0822x over previous
#include <cuda_runtime.h>
#include <cuda_bf16.h>
#include <math.h>
#include <stdint.h>

// MoE Router via warp-level bf16 mma.sync with 3-term split (near-fp32 accuracy):
// x = x1+x2+x3, w = w1+w2+w3 (bf16 levels); logits = sum of 6 cross terms >= 2^-24.
// T=16384, D=4096, E=64, top-2.
// Output (float32, concatenated):
//   [0, T*E)     logits [T,E]
//   [+T*2)       weights [T,2]
//   [+T*2)       indices [T,2] (as float)
//   [+E*2*T)     expert_mask [E,2,T]

#define Dk 4096
#define Ek 64
#define TOPK 2
#define BM 128        // tokens per CTA
#define KC 64         // k per chunk (64 bf16 = 128B row)
#define NCHUNK (Dk / KC)

// device scratch: pre-split gate weights (3 bf16 levels), [E][Dk] k-major
__device__ __nv_bfloat16 g_w1[Ek * Dk];
__device__ __nv_bfloat16 g_w2[Ek * Dk];
__device__ __nv_bfloat16 g_w3[Ek * Dk];

// ---------------- smem layout (dynamic) ----------------
#define SM_BIAS 64
#define BUF_STRIDE 73728          // 72KB per buffer
#define X1B(b) (1024 + (b) * BUF_STRIDE)
#define X2B(b) (X1B(b) + 16384)
#define X3B(b) (X2B(b) + 16384)
#define W1B(b) (X3B(b) + 16384)
#define W2B(b) (W1B(b) + 8192)
#define W3B(b) (W2B(b) + 8192)
#define SM_LG 1024                // 32KB logits scratch, reuses buf0 X area
#define SMEM_TOTAL (1024 + 2 * BUF_STRIDE)

// ---------------- helpers ----------------
__device__ __forceinline__ uint32_t smem_u32(const void* p) {
    uint32_t a;
    asm("{ .reg .u64 t; cvta.to.shared.u64 t, %1; cvt.u32.u64 %0, t; }" : "=r"(a) : "l"(p));
    return a;
}
// pack: hi -> upper 16, lo -> lower 16
__device__ __forceinline__ uint32_t pack2bf(float hi, float lo) {
    uint32_t r;
    asm("cvt.rn.bf16x2.f32 %0, %1, %2;" : "=r"(r) : "f"(hi), "f"(lo));
    return r;
}
// 3-level bf16 split of a float4 (memory order x,y / z,w packed pairs)
__device__ __forceinline__ void split4_3(float4 v, uint2& o1, uint2& o2, uint2& o3) {
    uint32_t a01 = pack2bf(v.y, v.x);
    uint32_t a23 = pack2bf(v.w, v.z);
    float rx = v.x - __uint_as_float(a01 << 16);
    float ry = v.y - __uint_as_float(a01 & 0xFFFF0000u);
    float rz = v.z - __uint_as_float(a23 << 16);
    float rw = v.w - __uint_as_float(a23 & 0xFFFF0000u);
    uint32_t b01 = pack2bf(ry, rx);
    uint32_t b23 = pack2bf(rw, rz);
    float sx = rx - __uint_as_float(b01 << 16);
    float sy = ry - __uint_as_float(b01 & 0xFFFF0000u);
    float sz = rz - __uint_as_float(b23 << 16);
    float sw = rw - __uint_as_float(b23 & 0xFFFF0000u);
    o1 = make_uint2(a01, a23);
    o2 = make_uint2(b01, b23);
    o3 = make_uint2(pack2bf(sy, sx), pack2bf(sw, sz));
}
__device__ __forceinline__ void ldm_x4(uint32_t* r, uint32_t addr) {
    asm volatile("ldmatrix.sync.aligned.m8n8.x4.shared.b16 {%0,%1,%2,%3}, [%4];"
        : "=r"(r[0]), "=r"(r[1]), "=r"(r[2]), "=r"(r[3]) : "r"(addr));
}
__device__ __forceinline__ void mma_bf16(float* c, const uint32_t* a, uint32_t b0, uint32_t b1) {
    asm volatile("mma.sync.aligned.m16n8k16.row.col.f32.bf16.bf16.f32 "
        "{%0,%1,%2,%3}, {%4,%5,%6,%7}, {%8,%9}, {%0,%1,%2,%3};"
        : "+f"(c[0]), "+f"(c[1]), "+f"(c[2]), "+f"(c[3])
        : "r"(a[0]), "r"(a[1]), "r"(a[2]), "r"(a[3]), "r"(b0), "r"(b1));
}

// ---------------- aux kernels ----------------
__global__ void zero_region_kernel(float4* __restrict__ p, int n4) {
    int i = blockIdx.x * blockDim.x + threadIdx.x;
    int stride = gridDim.x * blockDim.x;
    float4 z = make_float4(0.f, 0.f, 0.f, 0.f);
    for (; i < n4; i += stride) p[i] = z;
}

__global__ void w_split_kernel(const float4* __restrict__ gw4) {
    int i = blockIdx.x * blockDim.x + threadIdx.x;   // 65536 float4s
    uint2 a, b, c;
    split4_3(gw4[i], a, b, c);
    ((uint2*)g_w1)[i] = a;
    ((uint2*)g_w2)[i] = b;
    ((uint2*)g_w3)[i] = c;
}

// ---------------- main kernel ----------------
__global__ __launch_bounds__(256, 1)
void moe_router_mma(const float* __restrict__ x,
                    const float* __restrict__ gb,
                    float* __restrict__ out, int T)
{
    extern __shared__ char smem[];
    const uint32_t sb = smem_u32(smem);
    const int tid = threadIdx.x;
    const int lid = tid & 31;
    const int wid = tid >> 5;
    const int t0 = blockIdx.x * BM;

    if (tid < 16) ((float4*)(smem + SM_BIAS))[tid] = ((const float4*)gb)[tid];

    // ---- loader geometry ----
    const int xr = tid >> 4;   // x row group 0..15 (rows xr + 16*it)
    const int xj = tid & 15;   // 16B fp32-col group / 8B bf16 segment
    uint32_t x_sts[8];
#pragma unroll
    for (int it = 0; it < 8; ++it) {
        int row = xr + 16 * it;
        x_sts[it] = (uint32_t)(row * 128 + ((xj * 8) ^ ((row & 7) << 4)));
    }
    int wrow[2], wseg[2];
    uint32_t w_sts[2];
#pragma unroll
    for (int it = 0; it < 2; ++it) {
        int idx = it * 256 + tid;
        wrow[it] = idx >> 3; wseg[it] = idx & 7;
        w_sts[it] = (uint32_t)(wrow[it] * 128 + ((wseg[it] * 16) ^ ((wrow[it] & 7) << 4)));
    }

    // ---- mma geometry: warp tile 32(m) x 32(n) ----
    const int wm = wid & 3;              // token rows 32*wm..+31
    const int wn = wid >> 2;             // experts   32*wn..+31
    const int lrow = lid & 15;
    const int lhi = (lid >> 4) << 4;     // 0/16 bytes: k-half select for ldmatrix
    const int rsw = (lrow & 7) << 4;     // swizzle bits
    int arow[2], brow[2];
#pragma unroll
    for (int mi = 0; mi < 2; ++mi) arow[mi] = (32 * wm + 16 * mi + lrow) * 128;
#pragma unroll
    for (int g = 0; g < 2; ++g)  brow[g]  = (32 * wn + 16 * g + lrow) * 128;

    float acc[2][4][4];
#pragma unroll
    for (int mi = 0; mi < 2; ++mi)
#pragma unroll
        for (int nj = 0; nj < 4; ++nj)
#pragma unroll
            for (int q = 0; q < 4; ++q) acc[mi][nj][q] = 0.f;

    // ---- prologue: stage chunk 0 ----
    {
        const float* xp = x + (size_t)(t0 + xr) * Dk + 4 * xj;
#pragma unroll
        for (int it = 0; it < 8; ++it) {
            uint2 a, b2, c;
            split4_3(*(const float4*)(xp + (size_t)(16 * it) * Dk), a, b2, c);
            *(uint2*)(smem + X1B(0) + x_sts[it]) = a;
            *(uint2*)(smem + X2B(0) + x_sts[it]) = b2;
            *(uint2*)(smem + X3B(0) + x_sts[it]) = c;
        }
#pragma unroll
        for (int it = 0; it < 2; ++it) {
            const size_t eoff = (size_t)wrow[it] * Dk + wseg[it] * 8;
            *(uint4*)(smem + W1B(0) + w_sts[it]) = *(const uint4*)((const char*)g_w1 + eoff * 2);
            *(uint4*)(smem + W2B(0) + w_sts[it]) = *(const uint4*)((const char*)g_w2 + eoff * 2);
            *(uint4*)(smem + W3B(0) + w_sts[it]) = *(const uint4*)((const char*)g_w3 + eoff * 2);
        }
    }
    __syncthreads();

    // ---- main loop ----
    for (int c = 0; c < NCHUNK; ++c) {
        const int b = c & 1;
        const bool more = (c + 1 < NCHUNK);

        // 1) LDG next chunk into registers
        float4 xv[8];
        uint4 w1v[2], w2v[2], w3v[2];
        if (more) {
            const int d1 = (c + 1) * KC;
            const float* xp = x + (size_t)(t0 + xr) * Dk + d1 + 4 * xj;
#pragma unroll
            for (int it = 0; it < 8; ++it)
                xv[it] = *(const float4*)(xp + (size_t)(16 * it) * Dk);
#pragma unroll
            for (int it = 0; it < 2; ++it) {
                const size_t eoff = (size_t)wrow[it] * Dk + d1 + wseg[it] * 8;
                w1v[it] = *(const uint4*)((const char*)g_w1 + eoff * 2);
                w2v[it] = *(const uint4*)((const char*)g_w2 + eoff * 2);
                w3v[it] = *(const uint4*)((const char*)g_w3 + eoff * 2);
            }
        }

        // 2) compute current chunk from smem: 6 cross terms
        {
            const uint32_t x1_b = sb + X1B(b), x2_b = sb + X2B(b), x3_b = sb + X3B(b);
            const uint32_t w1_b = sb + W1B(b), w2_b = sb + W2B(b), w3_b = sb + W3B(b);
#pragma unroll
            for (int ks = 0; ks < 4; ++ks) {
                const uint32_t kb = (uint32_t)((ks * 32 + lhi) ^ rsw);
                uint32_t a1[2][4], a2[2][4], a3[2][4];
                uint32_t b1[2][4], b2[2][4], b3[2][4];
#pragma unroll
                for (int mi = 0; mi < 2; ++mi) {
                    ldm_x4(a1[mi], x1_b + arow[mi] + kb);
                    ldm_x4(a2[mi], x2_b + arow[mi] + kb);
                    ldm_x4(a3[mi], x3_b + arow[mi] + kb);
                }
#pragma unroll
                for (int g = 0; g < 2; ++g) {
                    ldm_x4(b1[g], w1_b + brow[g] + kb);
                    ldm_x4(b2[g], w2_b + brow[g] + kb);
                    ldm_x4(b3[g], w3_b + brow[g] + kb);
                }
#pragma unroll
                for (int mi = 0; mi < 2; ++mi)
#pragma unroll
                    for (int nj = 0; nj < 4; ++nj) {
                        const int g = nj >> 1, hf = nj & 1;
                        float* cc = acc[mi][nj];
                        mma_bf16(cc, a1[mi], b1[g][hf], b1[g][hf + 2]);
                        mma_bf16(cc, a1[mi], b2[g][hf], b2[g][hf + 2]);
                        mma_bf16(cc, a2[mi], b1[g][hf], b1[g][hf + 2]);
                        mma_bf16(cc, a2[mi], b2[g][hf], b2[g][hf + 2]);
                        mma_bf16(cc, a1[mi], b3[g][hf], b3[g][hf + 2]);
                        mma_bf16(cc, a3[mi], b1[g][hf], b1[g][hf + 2]);
                    }
            }
        }

        // 3) convert + store next chunk into other buffer
        if (more) {
            const int nb = 1 - b;
#pragma unroll
            for (int it = 0; it < 8; ++it) {
                uint2 a, b2s, cs;
                split4_3(xv[it], a, b2s, cs);
                *(uint2*)(smem + X1B(nb) + x_sts[it]) = a;
                *(uint2*)(smem + X2B(nb) + x_sts[it]) = b2s;
                *(uint2*)(smem + X3B(nb) + x_sts[it]) = cs;
            }
#pragma unroll
            for (int it = 0; it < 2; ++it) {
                *(uint4*)(smem + W1B(nb) + w_sts[it]) = w1v[it];
                *(uint4*)(smem + W2B(nb) + w_sts[it]) = w2v[it];
                *(uint4*)(smem + W3B(nb) + w_sts[it]) = w3v[it];
            }
        }
        __syncthreads();
    }

    // ---- epilogue: acc -> smem logits ----
    float* lg = (float*)(smem + SM_LG);
    {
        const int crow = 32 * wm + (lid >> 2);
        const int ccol = 32 * wn + (lid & 3) * 2;
#pragma unroll
        for (int mi = 0; mi < 2; ++mi)
#pragma unroll
            for (int nj = 0; nj < 4; ++nj) {
                const int r = crow + 16 * mi, cc = ccol + 8 * nj;
                *(float2*)&lg[r * Ek + cc]       = make_float2(acc[mi][nj][0], acc[mi][nj][1]);
                *(float2*)&lg[(r + 8) * Ek + cc] = make_float2(acc[mi][nj][2], acc[mi][nj][3]);
            }
    }
    __syncthreads();

    // pass 1: add bias, write logits to gmem, store biased values back to smem
    const float* bs = (const float*)(smem + SM_BIAS);
    {
        const int tl = tid >> 1, eh = (tid & 1) * 32;
        float* lr = lg + tl * Ek + eh;
        float4* orow = (float4*)(out + (size_t)(t0 + tl) * Ek + eh);
#pragma unroll
        for (int q = 0; q < 8; ++q) {
            float4 v = *(float4*)(lr + 4 * q);
            v.x += bs[eh + 4 * q + 0];
            v.y += bs[eh + 4 * q + 1];
            v.z += bs[eh + 4 * q + 2];
            v.w += bs[eh + 4 * q + 3];
            orow[q] = v;
            *(float4*)(lr + 4 * q) = v;
        }
    }
    __syncthreads();

    // pass 2: top-2, renorm weights, indices, mask scatter
    if (tid < BM) {
        const int t = t0 + tid;
        const float* lr = lg + tid * Ek;
        float m1 = -INFINITY, m2 = -INFINITY;
        int i1 = 0, i2 = 0;
#pragma unroll
        for (int e = 0; e < Ek; ++e) {
            float z = lr[e];
            if (z > m1) { m2 = m1; i2 = i1; m1 = z; i1 = e; }
            else if (z > m2) { m2 = z; i2 = e; }
        }
        float ed = expf(m2 - m1);
        float w1 = 1.0f / (1.0f + ed);
        float w2 = ed * w1;

        const size_t offW = (size_t)T * Ek;
        const size_t offI = offW + (size_t)T * TOPK;
        const size_t offM = offI + (size_t)T * TOPK;
        out[offW + (size_t)t * TOPK + 0] = w1;
        out[offW + (size_t)t * TOPK + 1] = w2;
        out[offI + (size_t)t * TOPK + 0] = (float)i1;
        out[offI + (size_t)t * TOPK + 1] = (float)i2;
        out[offM + ((size_t)i1 * TOPK + 0) * (size_t)T + t] = 1.0f;
        out[offM + ((size_t)i2 * TOPK + 1) * (size_t)T + t] = 1.0f;
    }
}

extern "C" void kernel_launch(void* const* d_in, const int* in_sizes, int n_in,
                              void* d_out, int out_size)
{
    const float* x  = (const float*)d_in[0];
    const float* gw = (const float*)d_in[1];
    const float* gb = (const float*)d_in[2];
    float* out = (float*)d_out;
    const int T = in_sizes[0] / Dk;

    cudaFuncSetAttribute(moe_router_mma, cudaFuncAttributeMaxDynamicSharedMemorySize, SMEM_TOTAL);

    // zero expert_mask region (rest of d_out fully overwritten)
    const size_t offM = (size_t)T * Ek + 2 * (size_t)T * TOPK;
    zero_region_kernel<<<592, 256>>>((float4*)(out + offM), (Ek * TOPK * T) / 4);

    // pre-split gate weights into 3 bf16 levels
    w_split_kernel<<<256, 256>>>((const float4*)gw);

    moe_router_mma<<<T / BM, 256, SMEM_TOTAL>>>(x, gb, out, T);
}

// round 10
// speedup vs baseline: 5.3268x; 1.7283x over previous
#include <cuda_runtime.h>
#include <cuda_fp16.h>
#include <math.h>
#include <stdint.h>

// MoE Router via warp-level fp16 mma.sync with 2-level fp16 split:
// x = x1+x2, w = w1+w2 (fp16 levels, 11-bit mantissa each);
// logits = x1*w1 + x1*w2 + x2*w1  (dropped x2*w2 ~ 2^-24) -> ~1e-7 accuracy.
// T=16384, D=4096, E=64, top-2.
// Output (float32, concatenated):
//   [0, T*E)     logits [T,E]
//   [+T*2)       weights [T,2]
//   [+T*2)       indices [T,2] (as float)
//   [+E*2*T)     expert_mask [E,2,T]

#define Dk 4096
#define Ek 64
#define TOPK 2
#define BM 128        // tokens per CTA
#define KC 64         // k per chunk (64 fp16 = 128B row)
#define NCHUNK (Dk / KC)

// device scratch: pre-split gate weights (2 fp16 levels), [E][Dk] k-major
__device__ __half g_w1[Ek * Dk];
__device__ __half g_w2[Ek * Dk];

// ---------------- smem layout (dynamic) ----------------
#define SM_BIAS 64
#define BUF_STRIDE 49152          // 48KB per buffer
#define X1B(b) (1024 + (b) * BUF_STRIDE)
#define X2B(b) (X1B(b) + 16384)
#define W1B(b) (X2B(b) + 16384)
#define W2B(b) (W1B(b) + 8192)
#define SM_LG 1024                // 32KB logits scratch, reuses buf0 X area
#define SMEM_TOTAL (1024 + 2 * BUF_STRIDE)

// ---------------- helpers ----------------
__device__ __forceinline__ uint32_t smem_u32(const void* p) {
    uint32_t a;
    asm("{ .reg .u64 t; cvta.to.shared.u64 t, %1; cvt.u32.u64 %0, t; }" : "=r"(a) : "l"(p));
    return a;
}
// pack two floats to f16x2: dest.hi = hi, dest.lo = lo
__device__ __forceinline__ uint32_t pack2h(float hi, float lo) {
    uint32_t r;
    asm("cvt.rn.f16x2.f32 %0, %1, %2;" : "=r"(r) : "f"(hi), "f"(lo));
    return r;
}
__device__ __forceinline__ float h_lo(uint32_t p) {
    float f;
    asm("{ .reg .b16 l, h; mov.b32 {l, h}, %1; cvt.f32.f16 %0, l; }" : "=f"(f) : "r"(p));
    return f;
}
__device__ __forceinline__ float h_hi(uint32_t p) {
    float f;
    asm("{ .reg .b16 l, h; mov.b32 {l, h}, %1; cvt.f32.f16 %0, h; }" : "=f"(f) : "r"(p));
    return f;
}
// 2-level fp16 split of float4; packed pairs in memory order (x,y) / (z,w)
__device__ __forceinline__ void split4_2(float4 v, uint2& o1, uint2& o2) {
    uint32_t a01 = pack2h(v.y, v.x);
    uint32_t a23 = pack2h(v.w, v.z);
    uint32_t b01 = pack2h(v.y - h_hi(a01), v.x - h_lo(a01));
    uint32_t b23 = pack2h(v.w - h_hi(a23), v.z - h_lo(a23));
    o1 = make_uint2(a01, a23);
    o2 = make_uint2(b01, b23);
}
__device__ __forceinline__ void ldm_x4(uint32_t* r, uint32_t addr) {
    asm volatile("ldmatrix.sync.aligned.m8n8.x4.shared.b16 {%0,%1,%2,%3}, [%4];"
        : "=r"(r[0]), "=r"(r[1]), "=r"(r[2]), "=r"(r[3]) : "r"(addr));
}
__device__ __forceinline__ void mma_f16(float* c, const uint32_t* a, uint32_t b0, uint32_t b1) {
    asm volatile("mma.sync.aligned.m16n8k16.row.col.f32.f16.f16.f32 "
        "{%0,%1,%2,%3}, {%4,%5,%6,%7}, {%8,%9}, {%0,%1,%2,%3};"
        : "+f"(c[0]), "+f"(c[1]), "+f"(c[2]), "+f"(c[3])
        : "r"(a[0]), "r"(a[1]), "r"(a[2]), "r"(a[3]), "r"(b0), "r"(b1));
}

// ---------------- aux kernels ----------------
__global__ void zero_region_kernel(float4* __restrict__ p, int n4) {
    int i = blockIdx.x * blockDim.x + threadIdx.x;
    int stride = gridDim.x * blockDim.x;
    float4 z = make_float4(0.f, 0.f, 0.f, 0.f);
    for (; i < n4; i += stride) p[i] = z;
}

__global__ void w_split_kernel(const float4* __restrict__ gw4) {
    int i = blockIdx.x * blockDim.x + threadIdx.x;   // 65536 float4s
    uint2 a, b;
    split4_2(gw4[i], a, b);
    ((uint2*)g_w1)[i] = a;
    ((uint2*)g_w2)[i] = b;
}

// ---------------- main kernel ----------------
__global__ __launch_bounds__(256, 1)
void moe_router_mma(const float* __restrict__ x,
                    const float* __restrict__ gb,
                    float* __restrict__ out, int T)
{
    extern __shared__ char smem[];
    const uint32_t sb = smem_u32(smem);
    const int tid = threadIdx.x;
    const int lid = tid & 31;
    const int wid = tid >> 5;
    const int t0 = blockIdx.x * BM;

    if (tid < 16) ((float4*)(smem + SM_BIAS))[tid] = ((const float4*)gb)[tid];

    // ---- loader geometry ----
    const int xr = tid >> 4;   // x row group 0..15 (rows xr + 16*it)
    const int xj = tid & 15;   // 16B fp32-col group / 8B fp16 segment
    uint32_t x_sts[8];
#pragma unroll
    for (int it = 0; it < 8; ++it) {
        int row = xr + 16 * it;
        x_sts[it] = (uint32_t)(row * 128 + ((xj * 8) ^ ((row & 7) << 4)));
    }
    int wrow[2], wseg[2];
    uint32_t w_sts[2];
#pragma unroll
    for (int it = 0; it < 2; ++it) {
        int idx = it * 256 + tid;
        wrow[it] = idx >> 3; wseg[it] = idx & 7;
        w_sts[it] = (uint32_t)(wrow[it] * 128 + ((wseg[it] * 16) ^ ((wrow[it] & 7) << 4)));
    }

    // ---- mma geometry: warp tile 32(m) x 32(n) ----
    const int wm = wid & 3;              // token rows 32*wm..+31
    const int wn = wid >> 2;             // experts   32*wn..+31
    const int lrow = lid & 15;
    const int lhi = (lid >> 4) << 4;     // 0/16 bytes: k-half select for ldmatrix
    const int rsw = (lrow & 7) << 4;     // swizzle bits
    int arow[2], brow[2];
#pragma unroll
    for (int mi = 0; mi < 2; ++mi) arow[mi] = (32 * wm + 16 * mi + lrow) * 128;
#pragma unroll
    for (int g = 0; g < 2; ++g)  brow[g]  = (32 * wn + 16 * g + lrow) * 128;

    float acc[2][4][4];
#pragma unroll
    for (int mi = 0; mi < 2; ++mi)
#pragma unroll
        for (int nj = 0; nj < 4; ++nj)
#pragma unroll
            for (int q = 0; q < 4; ++q) acc[mi][nj][q] = 0.f;

    // ---- prologue: stage chunk 0 ----
    {
        const float* xp = x + (size_t)(t0 + xr) * Dk + 4 * xj;
#pragma unroll
        for (int it = 0; it < 8; ++it) {
            uint2 a, b2;
            split4_2(*(const float4*)(xp + (size_t)(16 * it) * Dk), a, b2);
            *(uint2*)(smem + X1B(0) + x_sts[it]) = a;
            *(uint2*)(smem + X2B(0) + x_sts[it]) = b2;
        }
#pragma unroll
        for (int it = 0; it < 2; ++it) {
            const size_t eoff = (size_t)wrow[it] * Dk + wseg[it] * 8;
            *(uint4*)(smem + W1B(0) + w_sts[it]) = *(const uint4*)((const char*)g_w1 + eoff * 2);
            *(uint4*)(smem + W2B(0) + w_sts[it]) = *(const uint4*)((const char*)g_w2 + eoff * 2);
        }
    }
    __syncthreads();

    // ---- main loop ----
    for (int c = 0; c < NCHUNK; ++c) {
        const int b = c & 1;
        const bool more = (c + 1 < NCHUNK);

        // 1) LDG next chunk into registers
        float4 xv[8];
        uint4 w1v[2], w2v[2];
        if (more) {
            const int d1 = (c + 1) * KC;
            const float* xp = x + (size_t)(t0 + xr) * Dk + d1 + 4 * xj;
#pragma unroll
            for (int it = 0; it < 8; ++it)
                xv[it] = *(const float4*)(xp + (size_t)(16 * it) * Dk);
#pragma unroll
            for (int it = 0; it < 2; ++it) {
                const size_t eoff = (size_t)wrow[it] * Dk + d1 + wseg[it] * 8;
                w1v[it] = *(const uint4*)((const char*)g_w1 + eoff * 2);
                w2v[it] = *(const uint4*)((const char*)g_w2 + eoff * 2);
            }
        }

        // 2) compute current chunk from smem: 3 cross terms
        {
            const uint32_t x1_b = sb + X1B(b), x2_b = sb + X2B(b);
            const uint32_t w1_b = sb + W1B(b), w2_b = sb + W2B(b);
#pragma unroll
            for (int ks = 0; ks < 4; ++ks) {
                const uint32_t kb = (uint32_t)((ks * 32 + lhi) ^ rsw);
                uint32_t a1[2][4], a2[2][4], b1[2][4], b2[2][4];
#pragma unroll
                for (int mi = 0; mi < 2; ++mi) {
                    ldm_x4(a1[mi], x1_b + arow[mi] + kb);
                    ldm_x4(a2[mi], x2_b + arow[mi] + kb);
                }
#pragma unroll
                for (int g = 0; g < 2; ++g) {
                    ldm_x4(b1[g], w1_b + brow[g] + kb);
                    ldm_x4(b2[g], w2_b + brow[g] + kb);
                }
#pragma unroll
                for (int mi = 0; mi < 2; ++mi)
#pragma unroll
                    for (int nj = 0; nj < 4; ++nj) {
                        const int g = nj >> 1, hf = nj & 1;
                        float* cc = acc[mi][nj];
                        mma_f16(cc, a1[mi], b1[g][hf], b1[g][hf + 2]);
                        mma_f16(cc, a1[mi], b2[g][hf], b2[g][hf + 2]);
                        mma_f16(cc, a2[mi], b1[g][hf], b1[g][hf + 2]);
                    }
            }
        }

        // 3) convert + store next chunk into other buffer
        if (more) {
            const int nb = 1 - b;
#pragma unroll
            for (int it = 0; it < 8; ++it) {
                uint2 a, b2s;
                split4_2(xv[it], a, b2s);
                *(uint2*)(smem + X1B(nb) + x_sts[it]) = a;
                *(uint2*)(smem + X2B(nb) + x_sts[it]) = b2s;
            }
#pragma unroll
            for (int it = 0; it < 2; ++it) {
                *(uint4*)(smem + W1B(nb) + w_sts[it]) = w1v[it];
                *(uint4*)(smem + W2B(nb) + w_sts[it]) = w2v[it];
            }
        }
        __syncthreads();
    }

    // ---- epilogue: acc -> smem logits ----
    float* lg = (float*)(smem + SM_LG);
    {
        const int crow = 32 * wm + (lid >> 2);
        const int ccol = 32 * wn + (lid & 3) * 2;
#pragma unroll
        for (int mi = 0; mi < 2; ++mi)
#pragma unroll
            for (int nj = 0; nj < 4; ++nj) {
                const int r = crow + 16 * mi, cc = ccol + 8 * nj;
                *(float2*)&lg[r * Ek + cc]       = make_float2(acc[mi][nj][0], acc[mi][nj][1]);
                *(float2*)&lg[(r + 8) * Ek + cc] = make_float2(acc[mi][nj][2], acc[mi][nj][3]);
            }
    }
    __syncthreads();

    // pass 1: add bias, write logits to gmem, store biased values back to smem
    const float* bs = (const float*)(smem + SM_BIAS);
    {
        const int tl = tid >> 1, eh = (tid & 1) * 32;
        float* lr = lg + tl * Ek + eh;
        float4* orow = (float4*)(out + (size_t)(t0 + tl) * Ek + eh);
#pragma unroll
        for (int q = 0; q < 8; ++q) {
            float4 v = *(float4*)(lr + 4 * q);
            v.x += bs[eh + 4 * q + 0];
            v.y += bs[eh + 4 * q + 1];
            v.z += bs[eh + 4 * q + 2];
            v.w += bs[eh + 4 * q + 3];
            orow[q] = v;
            *(float4*)(lr + 4 * q) = v;
        }
    }
    __syncthreads();

    // pass 2: top-2, renorm weights, indices, mask scatter
    if (tid < BM) {
        const int t = t0 + tid;
        const float* lr = lg + tid * Ek;
        float m1 = -INFINITY, m2 = -INFINITY;
        int i1 = 0, i2 = 0;
#pragma unroll
        for (int e = 0; e < Ek; ++e) {
            float z = lr[e];
            if (z > m1) { m2 = m1; i2 = i1; m1 = z; i1 = e; }
            else if (z > m2) { m2 = z; i2 = e; }
        }
        float ed = expf(m2 - m1);
        float w1 = 1.0f / (1.0f + ed);
        float w2 = ed * w1;

        const size_t offW = (size_t)T * Ek;
        const size_t offI = offW + (size_t)T * TOPK;
        const size_t offM = offI + (size_t)T * TOPK;
        out[offW + (size_t)t * TOPK + 0] = w1;
        out[offW + (size_t)t * TOPK + 1] = w2;
        out[offI + (size_t)t * TOPK + 0] = (float)i1;
        out[offI + (size_t)t * TOPK + 1] = (float)i2;
        out[offM + ((size_t)i1 * TOPK + 0) * (size_t)T + t] = 1.0f;
        out[offM + ((size_t)i2 * TOPK + 1) * (size_t)T + t] = 1.0f;
    }
}

extern "C" void kernel_launch(void* const* d_in, const int* in_sizes, int n_in,
                              void* d_out, int out_size)
{
    const float* x  = (const float*)d_in[0];
    const float* gw = (const float*)d_in[1];
    const float* gb = (const float*)d_in[2];
    float* out = (float*)d_out;
    const int T = in_sizes[0] / Dk;

    cudaFuncSetAttribute(moe_router_mma, cudaFuncAttributeMaxDynamicSharedMemorySize, SMEM_TOTAL);

    // zero expert_mask region (rest of d_out fully overwritten)
    const size_t offM = (size_t)T * Ek + 2 * (size_t)T * TOPK;
    zero_region_kernel<<<592, 256>>>((float4*)(out + offM), (Ek * TOPK * T) / 4);

    // pre-split gate weights into 2 fp16 levels
    w_split_kernel<<<256, 256>>>((const float4*)gw);

    moe_router_mma<<<T / BM, 256, SMEM_TOTAL>>>(x, gb, out, T);
}